// round 8
// baseline (speedup 1.0000x reference)
#include <cuda_runtime.h>
#include <cuda_fp16.h>
#include <cstdint>

// Problem constants
#define BB   8
#define CIN  128
#define COUT 128
#define HH   128
#define WW   128
#define RNK  32
#define HW   (HH*WW)
#define K3   (3.0f/128.0f)

// Scratch (no allocation allowed)
__device__ float g_vproj[BB*CIN*16];      // (b, i, p*4+q)
__device__ float g_vr[BB*RNK];            // (b, r)
__device__ float g_mpart[4][BB*COUT*16];  // partial m over r-chunks
__device__ uint4 g_Wfrag[8][8][32];       // conv_w fp16 A-fragments
__device__ __half g_vh[(size_t)BB*CIN*HH*WW];  // fp16 copy of v (32MB)

__device__ __forceinline__ float hatf(float d) {
    return fmaxf(0.0f, 1.0f - fabsf(d));
}

__device__ __forceinline__ uint32_t packh2(float x, float y) {
    __half2 t = __floats2half2_rn(x, y);
    return *reinterpret_cast<uint32_t*>(&t);
}

// ============================================================================
// Kernel A: vproj[b,i,p,q] = sum_hw wy[h,p]*wx[w,q]*v[b,i,h,w]
//           + emit fp16 copy of v into g_vh
// grid = B*Cin, 256 threads, software-pipelined 4-row batches
// ============================================================================
__global__ __launch_bounds__(256, 4) void kA_vproj(const float* __restrict__ v) {
    const int tid  = threadIdx.x;
    const int wid  = tid >> 5;
    const int lane = tid & 31;
    const float* vb = v + (size_t)blockIdx.x * HW;
    __half* vhb = g_vh + (size_t)blockIdx.x * HW;

    float wxr[4][4];
#pragma unroll
    for (int c = 0; c < 4; c++) {
        float tx = ((lane << 2) + c + 0.5f) * K3;
#pragma unroll
        for (int q = 0; q < 4; q++) wxr[c][q] = hatf(tx - (float)q);
    }

    float acc[16];
#pragma unroll
    for (int t = 0; t < 16; t++) acc[t] = 0.0f;

    float4 cur[4], nxt[4];
#pragma unroll
    for (int j = 0; j < 4; j++)
        cur[j] = *reinterpret_cast<const float4*>(vb + ((wid << 4) + j) * WW + (lane << 2));

#pragma unroll
    for (int bt = 0; bt < 4; bt++) {
        if (bt < 3) {
#pragma unroll
            for (int j = 0; j < 4; j++)
                nxt[j] = *reinterpret_cast<const float4*>(
                    vb + ((wid << 4) + (bt + 1) * 4 + j) * WW + (lane << 2));
        }
#pragma unroll
        for (int j = 0; j < 4; j++) {
            const int r = (wid << 4) + bt * 4 + j;
            const float vals[4] = {cur[j].x, cur[j].y, cur[j].z, cur[j].w};
            // fp16 copy (coalesced 8B per lane)
            uint2 hh;
            hh.x = packh2(vals[0], vals[1]);
            hh.y = packh2(vals[2], vals[3]);
            *reinterpret_cast<uint2*>(vhb + r * WW + (lane << 2)) = hh;

            float s[4] = {0.f, 0.f, 0.f, 0.f};
#pragma unroll
            for (int c = 0; c < 4; c++) {
#pragma unroll
                for (int q = 0; q < 4; q++) s[q] += vals[c] * wxr[c][q];
            }
            float ty = (r + 0.5f) * K3;
#pragma unroll
            for (int p = 0; p < 4; p++) {
                float hp = hatf(ty - (float)p);
#pragma unroll
                for (int q = 0; q < 4; q++) acc[p * 4 + q] += hp * s[q];
            }
        }
#pragma unroll
        for (int j = 0; j < 4; j++) cur[j] = nxt[j];
    }

#pragma unroll
    for (int t = 0; t < 16; t++) {
#pragma unroll
        for (int off = 16; off > 0; off >>= 1)
            acc[t] += __shfl_xor_sync(0xFFFFFFFFu, acc[t], off);
    }
    __shared__ float red[8][16];
    if (lane == 0) {
#pragma unroll
        for (int t = 0; t < 16; t++) red[wid][t] = acc[t];
    }
    __syncthreads();
    if (tid < 16) {
        float s = 0.f;
#pragma unroll
        for (int w = 0; w < 8; w++) s += red[w][tid];
        g_vproj[blockIdx.x * 16 + tid] = s;
    }
}

// ============================================================================
// Kernel B1 (+ W-pack merged): grid (33, 8), 256 threads
// ============================================================================
__global__ __launch_bounds__(256) void kB1W(const float* __restrict__ k1,
                                            const float* __restrict__ cw) {
    const int tid = threadIdx.x;
    if (blockIdx.x == 32) {
        const int idx = blockIdx.y * 256 + tid;   // 0..2047
        const int ot = idx >> 8, ks = (idx >> 5) & 7, lane = idx & 31;
        const int r0 = ot * 16 + (lane >> 2), r1 = r0 + 8;
        const int kb = ks * 16 + (lane & 3) * 2;
        uint4 f;
        f.x = packh2(cw[r0 * CIN + kb],     cw[r0 * CIN + kb + 1]);
        f.y = packh2(cw[r1 * CIN + kb],     cw[r1 * CIN + kb + 1]);
        f.z = packh2(cw[r0 * CIN + kb + 8], cw[r0 * CIN + kb + 9]);
        f.w = packh2(cw[r1 * CIN + kb + 8], cw[r1 * CIN + kb + 9]);
        g_Wfrag[ot][ks][lane] = f;
        return;
    }
    const int r = blockIdx.x, b = blockIdx.y;
    const int wid = tid >> 5, lane = tid & 31;
    const float* k1p = k1 + (size_t)r * (CIN * 16);
    const float* vpp = g_vproj + (size_t)b * (CIN * 16);

    float s = 0.f;
#pragma unroll
    for (int j = 0; j < 2; j++) {
        const int e = (j * 256 + tid) * 4;
        float4 a = *reinterpret_cast<const float4*>(k1p + e);
        float4 c = *reinterpret_cast<const float4*>(vpp + e);
        s += a.x * c.x + a.y * c.y + a.z * c.z + a.w * c.w;
    }
#pragma unroll
    for (int off = 16; off > 0; off >>= 1)
        s += __shfl_xor_sync(0xFFFFFFFFu, s, off);
    __shared__ float red[8];
    if (lane == 0) red[wid] = s;
    __syncthreads();
    if (tid == 0) {
        float t = 0.f;
#pragma unroll
        for (int w = 0; w < 8; w++) t += red[w];
        g_vr[b * RNK + r] = t * (1.0f / (float)HW);
    }
}

// ============================================================================
// Kernel B2: partial m over r-chunks of 8: grid (8, 4, B)
// ============================================================================
__global__ __launch_bounds__(256) void kB2_m(const float* __restrict__ k2) {
    const int ch = blockIdx.x, rc = blockIdx.y, b = blockIdx.z, tid = threadIdx.x;
    __shared__ float vr[8];
    if (tid < 8) vr[tid] = g_vr[b * RNK + rc * 8 + tid];
    __syncthreads();

    const int idx = ch * 256 + tid;
    float s = 0.f;
#pragma unroll
    for (int j = 0; j < 8; j++)
        s += k2[(size_t)(rc * 8 + j) * (COUT * 16) + idx] * vr[j];
    g_mpart[rc][b * (COUT * 16) + idx] = s;
}

// ============================================================================
// Kernel C: out = conv_w@v (fp16 HMMA) + interp(m) + biases
// grid = (h=128, b=8), 256 threads (8 warps: 4 o-tiles x 2 w-tiles of 32x64)
// cp.async fp16 gmem -> XOR-swizzled smem, 3-stage pipeline.
// ============================================================================

#define LDSM4T(r0, r1, r2, r3, addr)                                            \
    asm volatile("ldmatrix.sync.aligned.m8n8.x4.trans.shared.b16 {%0,%1,%2,%3}, [%4];" \
                 : "=r"(r0), "=r"(r1), "=r"(r2), "=r"(r3) : "r"(addr))

#define MMAF16(d, a0, a1, a2, a3, b0, b1)                                  \
    asm volatile("mma.sync.aligned.m16n8k16.row.col.f32.f16.f16.f32 "      \
                 "{%0,%1,%2,%3}, {%4,%5,%6,%7}, {%8,%9}, {%0,%1,%2,%3};"   \
                 : "+f"(d[0]), "+f"(d[1]), "+f"(d[2]), "+f"(d[3])          \
                 : "r"(a0), "r"(a1), "r"(a2), "r"(a3), "r"(b0), "r"(b1))

#define CP_ASYNC16(dst, src) \
    asm volatile("cp.async.cg.shared.global [%0], [%1], 16;" :: "r"(dst), "l"(src))
#define CP_COMMIT()  asm volatile("cp.async.commit_group;")
#define CP_WAIT1()   asm volatile("cp.async.wait_group 1;")

__global__ __launch_bounds__(256, 2) void kC_fp16(const float* __restrict__ conv_b,
                                                  const float* __restrict__ bias,
                                                  float* __restrict__ out) {
    // 3 bufs x 32 k-rows x 128 w (fp16): 256B rows, 16B chunks XOR-swizzled
    __shared__ __align__(16) __half sB[3][32][128];
    __shared__ __align__(16) float sM2[128][4];
    __shared__ float sCB[128];

    const int h = blockIdx.x, b = blockIdx.y;
    const int tid = threadIdx.x, wid = tid >> 5, lane = tid & 31;
    const int o_base = (wid & 3) * 32;
    const int w_base = (wid >> 2) * 64;
    const int ot0 = (wid & 3) * 2;

    // load slot: krow = tid>>3 (0..31), seg = tid&7 (16 halves = 32B each)
    const int krow = tid >> 3;
    const int seg  = tid & 7;
    const int sw = krow & 7;
    const __half* vhbase = g_vh + (((size_t)b * CIN + krow) * HH + h) * WW + seg * 16;
    const uint32_t sBbase = (uint32_t)__cvta_generic_to_shared(&sB[0][0][0]);

    // issue chunks 0 and 1
#pragma unroll
    for (int pc = 0; pc < 2; pc++) {
        const __half* src = vhbase + (size_t)pc * 32 * HW;
        const uint32_t rowb = sBbase + (uint32_t)(pc * 8192 + krow * 256);
#pragma unroll
        for (int c = 0; c < 2; c++) {
            CP_ASYNC16(rowb + (uint32_t)((((seg << 1) + c) ^ sw) * 16), src + c * 8);
        }
        CP_COMMIT();
    }

    // prologue: M2[o][q] = sum_p wy[h,p]*m[b,o,p*4+q] (m = sum of 4 partials)
    {
        const float ty = (h + 0.5f) * K3;
        const float wy0 = hatf(ty), wy1 = hatf(ty - 1.f);
        const float wy2 = hatf(ty - 2.f), wy3 = hatf(ty - 3.f);
        for (int idx = tid; idx < 512; idx += 256) {
            const int o = idx >> 2, q = idx & 3;
            const int base = b * (COUT * 16) + o * 16 + q;
            float m0 = 0.f, m1 = 0.f, m2 = 0.f, m3 = 0.f;
#pragma unroll
            for (int rc = 0; rc < 4; rc++) {
                const float* mp = &g_mpart[rc][base];
                m0 += mp[0]; m1 += mp[4]; m2 += mp[8]; m3 += mp[12];
            }
            sM2[o][q] = wy0 * m0 + wy1 * m1 + wy2 * m2 + wy3 * m3;
        }
        if (tid < 128) sCB[tid] = conv_b[tid] + bias[tid];
    }

    float acc[2][8][4];
#pragma unroll
    for (int mi = 0; mi < 2; mi++)
#pragma unroll
        for (int ni = 0; ni < 8; ni++)
#pragma unroll
            for (int c = 0; c < 4; c++) acc[mi][ni][c] = 0.0f;

    for (int kc = 0; kc < 4; kc++) {
        const int buf = kc % 3;
        CP_WAIT1();          // this thread's chunk kc landed
        __syncthreads();     // all threads' chunk kc visible; MMA(kc-1) done

        // issue chunk kc+2 into buffer (kc+2)%3 (freed by the barrier)
        if (kc < 2) {
            const int pc = kc + 2;
            const __half* src = vhbase + (size_t)pc * 32 * HW;
            const uint32_t rowb = sBbase + (uint32_t)((pc % 3) * 8192 + krow * 256);
#pragma unroll
            for (int c = 0; c < 2; c++) {
                CP_ASYNC16(rowb + (uint32_t)((((seg << 1) + c) ^ sw) * 16), src + c * 8);
            }
            CP_COMMIT();
        } else {
            CP_COMMIT();     // keep group accounting uniform for CP_WAIT1
        }

#pragma unroll
        for (int ks = 0; ks < 2; ks++) {
            const int gks = kc * 2 + ks;
            uint4 A0 = g_Wfrag[ot0 + 0][gks][lane];
            uint4 A1 = g_Wfrag[ot0 + 1][gks][lane];
            const int kr = ks * 16 + (lane & 15);
            const uint32_t rowoff = (uint32_t)(buf * 8192 + kr * 256);
            const int cb = (w_base >> 3) + (lane >> 4);
#pragma unroll
            for (int ng = 0; ng < 4; ng++) {
                const int chunk = (cb + ng * 2) ^ (kr & 7);
                uint32_t b0, b1, b2, b3;
                LDSM4T(b0, b1, b2, b3, sBbase + rowoff + (uint32_t)(chunk * 16));
                float* d00 = acc[0][ng * 2 + 0];
                float* d01 = acc[0][ng * 2 + 1];
                float* d10 = acc[1][ng * 2 + 0];
                float* d11 = acc[1][ng * 2 + 1];
                MMAF16(d00, A0.x, A0.y, A0.z, A0.w, b0, b1);
                MMAF16(d01, A0.x, A0.y, A0.z, A0.w, b2, b3);
                MMAF16(d10, A1.x, A1.y, A1.z, A1.w, b0, b1);
                MMAF16(d11, A1.x, A1.y, A1.z, A1.w, b2, b3);
            }
        }
    }

    // epilogue: add interp term + biases, store
    const int g = lane >> 2, cq = lane & 3;
#pragma unroll
    for (int ni = 0; ni < 8; ni++) {
        const int w0 = w_base + ni * 8 + cq * 2;
        const float tx0 = (w0 + 0.5f) * K3, tx1 = tx0 + K3;
        float wxa[4], wxb[4];
#pragma unroll
        for (int q = 0; q < 4; q++) {
            wxa[q] = hatf(tx0 - (float)q);
            wxb[q] = hatf(tx1 - (float)q);
        }
#pragma unroll
        for (int mi = 0; mi < 2; mi++) {
#pragma unroll
            for (int rr = 0; rr < 2; rr++) {
                const int o = o_base + mi * 16 + g + rr * 8;
                float4 m2 = *reinterpret_cast<float4*>(&sM2[o][0]);
                const float base = sCB[o];
                float t0 = base + wxa[0] * m2.x + wxa[1] * m2.y + wxa[2] * m2.z + wxa[3] * m2.w;
                float t1 = base + wxb[0] * m2.x + wxb[1] * m2.y + wxb[2] * m2.z + wxb[3] * m2.w;
                float2 res;
                res.x = acc[mi][ni][rr * 2 + 0] + t0;
                res.y = acc[mi][ni][rr * 2 + 1] + t1;
                *reinterpret_cast<float2*>(out + (((size_t)b * COUT + o) * HH + h) * WW + w0) = res;
            }
        }
    }
}

// ============================================================================
extern "C" void kernel_launch(void* const* d_in, const int* in_sizes, int n_in,
                              void* d_out, int out_size) {
    const float* v      = (const float*)d_in[0];
    const float* k1     = (const float*)d_in[1];
    const float* k2     = (const float*)d_in[2];
    const float* conv_w = (const float*)d_in[3];
    const float* conv_b = (const float*)d_in[4];
    const float* bias   = (const float*)d_in[5];
    float* out = (float*)d_out;

    kA_vproj<<<BB * CIN, 256>>>(v);
    kB1W<<<dim3(33, BB), 256>>>(k1, conv_w);
    kB2_m<<<dim3(8, 4, BB), 256>>>(k2);
    kC_fp16<<<dim3(HH, BB), 256>>>(conv_b, bias, out);
}

// round 9
// speedup vs baseline: 1.1690x; 1.1690x over previous
#include <cuda_runtime.h>
#include <cuda_fp16.h>
#include <cstdint>

// Problem constants
#define BB   8
#define CIN  128
#define COUT 128
#define HH   128
#define WW   128
#define RNK  32
#define HW   (HH*WW)
#define K3   (3.0f/128.0f)

// Scratch (no allocation allowed)
__device__ float g_vproj[BB*CIN*16];      // (b, i, p*4+q)
__device__ float g_vr[BB*RNK];            // (b, r)
__device__ float g_mpart[4][BB*COUT*16];  // partial m over r-chunks
__device__ uint4 g_Wfrag[8][8][32];       // conv_w fp16 A-fragments
__device__ __half g_vh[(size_t)BB*CIN*HH*WW];  // fp16 copy of v (32MB)

__device__ __forceinline__ float hatf(float d) {
    return fmaxf(0.0f, 1.0f - fabsf(d));
}

__device__ __forceinline__ uint32_t packh2(float x, float y) {
    __half2 t = __floats2half2_rn(x, y);
    return *reinterpret_cast<uint32_t*>(&t);
}

// ============================================================================
// Kernel A: vproj[b,i,p,q] = sum_hw wy[h,p]*wx[w,q]*v[b,i,h,w]
//           + emit fp16 copy of v into g_vh
// grid = B*Cin, 256 threads; all 16 row-loads issued up front (MLP=16)
// ============================================================================
__global__ __launch_bounds__(256) void kA_vproj(const float* __restrict__ v) {
    const int tid  = threadIdx.x;
    const int wid  = tid >> 5;
    const int lane = tid & 31;
    const float* vb = v + (size_t)blockIdx.x * HW;
    __half* vhb = g_vh + (size_t)blockIdx.x * HW;

    float wxr[4][4];
#pragma unroll
    for (int c = 0; c < 4; c++) {
        float tx = ((lane << 2) + c + 0.5f) * K3;
#pragma unroll
        for (int q = 0; q < 4; q++) wxr[c][q] = hatf(tx - (float)q);
    }

    float acc[16];
#pragma unroll
    for (int t = 0; t < 16; t++) acc[t] = 0.0f;

    // issue all 16 row loads up front for max MLP
    float4 rows[16];
#pragma unroll
    for (int rr = 0; rr < 16; rr++) {
        const int r = (wid << 4) + rr;
        rows[rr] = *reinterpret_cast<const float4*>(vb + r * WW + (lane << 2));
    }

#pragma unroll
    for (int rr = 0; rr < 16; rr++) {
        const int r = (wid << 4) + rr;
        const float vals[4] = {rows[rr].x, rows[rr].y, rows[rr].z, rows[rr].w};
        // fp16 copy (coalesced 8B per lane)
        uint2 hh;
        hh.x = packh2(vals[0], vals[1]);
        hh.y = packh2(vals[2], vals[3]);
        *reinterpret_cast<uint2*>(vhb + r * WW + (lane << 2)) = hh;

        float s[4] = {0.f, 0.f, 0.f, 0.f};
#pragma unroll
        for (int c = 0; c < 4; c++) {
#pragma unroll
            for (int q = 0; q < 4; q++) s[q] += vals[c] * wxr[c][q];
        }
        float ty = (r + 0.5f) * K3;
#pragma unroll
        for (int p = 0; p < 4; p++) {
            float hp = hatf(ty - (float)p);
#pragma unroll
            for (int q = 0; q < 4; q++) acc[p * 4 + q] += hp * s[q];
        }
    }

#pragma unroll
    for (int t = 0; t < 16; t++) {
#pragma unroll
        for (int off = 16; off > 0; off >>= 1)
            acc[t] += __shfl_xor_sync(0xFFFFFFFFu, acc[t], off);
    }
    __shared__ float red[8][16];
    if (lane == 0) {
#pragma unroll
        for (int t = 0; t < 16; t++) red[wid][t] = acc[t];
    }
    __syncthreads();
    if (tid < 16) {
        float s = 0.f;
#pragma unroll
        for (int w = 0; w < 8; w++) s += red[w][tid];
        g_vproj[blockIdx.x * 16 + tid] = s;
    }
}

// ============================================================================
// Kernel B1 (+ W-pack merged): grid (33, 8), 256 threads
// ============================================================================
__global__ __launch_bounds__(256) void kB1W(const float* __restrict__ k1,
                                            const float* __restrict__ cw) {
    const int tid = threadIdx.x;
    if (blockIdx.x == 32) {
        const int idx = blockIdx.y * 256 + tid;   // 0..2047
        const int ot = idx >> 8, ks = (idx >> 5) & 7, lane = idx & 31;
        const int r0 = ot * 16 + (lane >> 2), r1 = r0 + 8;
        const int kb = ks * 16 + (lane & 3) * 2;
        uint4 f;
        f.x = packh2(cw[r0 * CIN + kb],     cw[r0 * CIN + kb + 1]);
        f.y = packh2(cw[r1 * CIN + kb],     cw[r1 * CIN + kb + 1]);
        f.z = packh2(cw[r0 * CIN + kb + 8], cw[r0 * CIN + kb + 9]);
        f.w = packh2(cw[r1 * CIN + kb + 8], cw[r1 * CIN + kb + 9]);
        g_Wfrag[ot][ks][lane] = f;
        return;
    }
    const int r = blockIdx.x, b = blockIdx.y;
    const int wid = tid >> 5, lane = tid & 31;
    const float* k1p = k1 + (size_t)r * (CIN * 16);
    const float* vpp = g_vproj + (size_t)b * (CIN * 16);

    float s = 0.f;
#pragma unroll
    for (int j = 0; j < 2; j++) {
        const int e = (j * 256 + tid) * 4;
        float4 a = *reinterpret_cast<const float4*>(k1p + e);
        float4 c = *reinterpret_cast<const float4*>(vpp + e);
        s += a.x * c.x + a.y * c.y + a.z * c.z + a.w * c.w;
    }
#pragma unroll
    for (int off = 16; off > 0; off >>= 1)
        s += __shfl_xor_sync(0xFFFFFFFFu, s, off);
    __shared__ float red[8];
    if (lane == 0) red[wid] = s;
    __syncthreads();
    if (tid == 0) {
        float t = 0.f;
#pragma unroll
        for (int w = 0; w < 8; w++) t += red[w];
        g_vr[b * RNK + r] = t * (1.0f / (float)HW);
    }
}

// ============================================================================
// Kernel B2: partial m over r-chunks of 8: grid (8, 4, B)
// ============================================================================
__global__ __launch_bounds__(256) void kB2_m(const float* __restrict__ k2) {
    const int ch = blockIdx.x, rc = blockIdx.y, b = blockIdx.z, tid = threadIdx.x;
    __shared__ float vr[8];
    if (tid < 8) vr[tid] = g_vr[b * RNK + rc * 8 + tid];
    __syncthreads();

    const int idx = ch * 256 + tid;
    float s = 0.f;
#pragma unroll
    for (int j = 0; j < 8; j++)
        s += k2[(size_t)(rc * 8 + j) * (COUT * 16) + idx] * vr[j];
    g_mpart[rc][b * (COUT * 16) + idx] = s;
}

// ============================================================================
// Kernel C: out = conv_w@v (fp16 HMMA) + interp(m) + biases
// grid = (h=128, wh=2, b=8), 256 threads (8 warps: 4 o-tiles x 2 w-tiles, 32x32)
// cp.async fp16 gmem -> XOR-swizzled smem, 3-stage pipeline, 3 CTAs/SM.
// ============================================================================

#define LDSM4T(r0, r1, r2, r3, addr)                                            \
    asm volatile("ldmatrix.sync.aligned.m8n8.x4.trans.shared.b16 {%0,%1,%2,%3}, [%4];" \
                 : "=r"(r0), "=r"(r1), "=r"(r2), "=r"(r3) : "r"(addr))

#define MMAF16(d, a0, a1, a2, a3, b0, b1)                                  \
    asm volatile("mma.sync.aligned.m16n8k16.row.col.f32.f16.f16.f32 "      \
                 "{%0,%1,%2,%3}, {%4,%5,%6,%7}, {%8,%9}, {%0,%1,%2,%3};"   \
                 : "+f"(d[0]), "+f"(d[1]), "+f"(d[2]), "+f"(d[3])          \
                 : "r"(a0), "r"(a1), "r"(a2), "r"(a3), "r"(b0), "r"(b1))

#define CP_ASYNC16(dst, src) \
    asm volatile("cp.async.cg.shared.global [%0], [%1], 16;" :: "r"(dst), "l"(src))
#define CP_COMMIT()  asm volatile("cp.async.commit_group;")
#define CP_WAIT1()   asm volatile("cp.async.wait_group 1;")

__global__ __launch_bounds__(256, 3) void kC_fp16(const float* __restrict__ conv_b,
                                                  const float* __restrict__ bias,
                                                  float* __restrict__ out) {
    // 3 bufs x 32 k-rows x 64 w (fp16): 128B rows, 8 chunks of 16B, XOR swizzle
    __shared__ __align__(16) __half sB[3][32][64];
    __shared__ __align__(16) float sM2[128][4];
    __shared__ float sCB[128];

    const int h = blockIdx.x, wh = blockIdx.y, b = blockIdx.z;
    const int tid = threadIdx.x, wid = tid >> 5, lane = tid & 31;
    const int o_base = (wid & 3) * 32;
    const int wloc   = (wid >> 2) * 32;
    const int ot0 = (wid & 3) * 2;

    // load slot: krow = tid>>3 (0..31), cseg = tid&7 (one 16B chunk each)
    const int krow = tid >> 3;
    const int cseg = tid & 7;
    const int sw = krow & 7;
    const __half* vhbase = g_vh + (((size_t)b * CIN + krow) * HH + h) * WW + wh * 64 + cseg * 8;
    const uint32_t sBbase = (uint32_t)__cvta_generic_to_shared(&sB[0][0][0]);
    const uint32_t mydst = (uint32_t)(krow * 128 + (cseg ^ sw) * 16);

    // issue chunks 0 and 1
#pragma unroll
    for (int pc = 0; pc < 2; pc++) {
        CP_ASYNC16(sBbase + (uint32_t)(pc * 4096) + mydst, vhbase + (size_t)pc * 32 * HW);
        CP_COMMIT();
    }

    // prologue: M2[o][q] = sum_p wy[h,p]*m[b,o,p*4+q] (m = sum of 4 partials)
    {
        const float ty = (h + 0.5f) * K3;
        const float wy0 = hatf(ty), wy1 = hatf(ty - 1.f);
        const float wy2 = hatf(ty - 2.f), wy3 = hatf(ty - 3.f);
        for (int idx = tid; idx < 512; idx += 256) {
            const int o = idx >> 2, q = idx & 3;
            const int base = b * (COUT * 16) + o * 16 + q;
            float m0 = 0.f, m1 = 0.f, m2 = 0.f, m3 = 0.f;
#pragma unroll
            for (int rc = 0; rc < 4; rc++) {
                const float* mp = &g_mpart[rc][base];
                m0 += mp[0]; m1 += mp[4]; m2 += mp[8]; m3 += mp[12];
            }
            sM2[o][q] = wy0 * m0 + wy1 * m1 + wy2 * m2 + wy3 * m3;
        }
        if (tid < 128) sCB[tid] = conv_b[tid] + bias[tid];
    }

    float acc[2][4][4];
#pragma unroll
    for (int mi = 0; mi < 2; mi++)
#pragma unroll
        for (int ni = 0; ni < 4; ni++)
#pragma unroll
            for (int c = 0; c < 4; c++) acc[mi][ni][c] = 0.0f;

    for (int kc = 0; kc < 4; kc++) {
        const int buf = kc % 3;
        CP_WAIT1();          // chunk kc landed (for this thread's group)
        __syncthreads();     // all threads' chunk kc visible; MMA(kc-1) done

        // issue chunk kc+2 into buffer (kc+2)%3 (freed by the barrier)
        if (kc < 2) {
            CP_ASYNC16(sBbase + (uint32_t)(((kc + 2) % 3) * 4096) + mydst,
                       vhbase + (size_t)(kc + 2) * 32 * HW);
        }
        CP_COMMIT();         // uniform group accounting for CP_WAIT1

#pragma unroll
        for (int ks = 0; ks < 2; ks++) {
            const int gks = kc * 2 + ks;
            uint4 A0 = g_Wfrag[ot0 + 0][gks][lane];
            uint4 A1 = g_Wfrag[ot0 + 1][gks][lane];
            const int kr = ks * 16 + (lane & 15);
            const uint32_t rowoff = (uint32_t)(buf * 4096 + kr * 128);
            const int cb = (wloc >> 3) + (lane >> 4);
#pragma unroll
            for (int ng = 0; ng < 2; ng++) {
                const int chunk = (cb + ng * 2) ^ (kr & 7);
                uint32_t b0, b1, b2, b3;
                LDSM4T(b0, b1, b2, b3, sBbase + rowoff + (uint32_t)(chunk * 16));
                float* d00 = acc[0][ng * 2 + 0];
                float* d01 = acc[0][ng * 2 + 1];
                float* d10 = acc[1][ng * 2 + 0];
                float* d11 = acc[1][ng * 2 + 1];
                MMAF16(d00, A0.x, A0.y, A0.z, A0.w, b0, b1);
                MMAF16(d01, A0.x, A0.y, A0.z, A0.w, b2, b3);
                MMAF16(d10, A1.x, A1.y, A1.z, A1.w, b0, b1);
                MMAF16(d11, A1.x, A1.y, A1.z, A1.w, b2, b3);
            }
        }
    }

    // epilogue: add interp term + biases, store
    const int g = lane >> 2, cq = lane & 3;
#pragma unroll
    for (int ni = 0; ni < 4; ni++) {
        const int w0 = wh * 64 + wloc + ni * 8 + cq * 2;
        const float tx0 = (w0 + 0.5f) * K3, tx1 = tx0 + K3;
        float wxa[4], wxb[4];
#pragma unroll
        for (int q = 0; q < 4; q++) {
            wxa[q] = hatf(tx0 - (float)q);
            wxb[q] = hatf(tx1 - (float)q);
        }
#pragma unroll
        for (int mi = 0; mi < 2; mi++) {
#pragma unroll
            for (int rr = 0; rr < 2; rr++) {
                const int o = o_base + mi * 16 + g + rr * 8;
                float4 m2 = *reinterpret_cast<float4*>(&sM2[o][0]);
                const float base = sCB[o];
                float t0 = base + wxa[0] * m2.x + wxa[1] * m2.y + wxa[2] * m2.z + wxa[3] * m2.w;
                float t1 = base + wxb[0] * m2.x + wxb[1] * m2.y + wxb[2] * m2.z + wxb[3] * m2.w;
                float2 res;
                res.x = acc[mi][ni][rr * 2 + 0] + t0;
                res.y = acc[mi][ni][rr * 2 + 1] + t1;
                *reinterpret_cast<float2*>(out + (((size_t)b * COUT + o) * HH + h) * WW + w0) = res;
            }
        }
    }
}

// ============================================================================
extern "C" void kernel_launch(void* const* d_in, const int* in_sizes, int n_in,
                              void* d_out, int out_size) {
    const float* v      = (const float*)d_in[0];
    const float* k1     = (const float*)d_in[1];
    const float* k2     = (const float*)d_in[2];
    const float* conv_w = (const float*)d_in[3];
    const float* conv_b = (const float*)d_in[4];
    const float* bias   = (const float*)d_in[5];
    float* out = (float*)d_out;

    kA_vproj<<<BB * CIN, 256>>>(v);
    kB1W<<<dim3(33, BB), 256>>>(k1, conv_w);
    kB2_m<<<dim3(8, 4, BB), 256>>>(k2);
    kC_fp16<<<dim3(HH, 2, BB), 256>>>(conv_b, bias, out);
}

// round 10
// speedup vs baseline: 1.2454x; 1.0654x over previous
#include <cuda_runtime.h>
#include <cuda_fp16.h>
#include <cstdint>

// Problem constants
#define BB   8
#define CIN  128
#define COUT 128
#define HH   128
#define WW   128
#define RNK  32
#define HW   (HH*WW)
#define K3   (3.0f/128.0f)

// Scratch (no allocation allowed)
__device__ float g_vproj[BB*CIN*16];      // (b, i, p*4+q)
__device__ float g_vr[BB*RNK];            // (b, r)
__device__ float g_mpart[4][BB*COUT*16];  // partial m over r-chunks
__device__ uint4 g_Wfrag[8][8][32];       // conv_w fp16 A-fragments
__device__ __half g_vh[(size_t)BB*CIN*HH*WW];  // fp16 copy of v (32MB)

__device__ __forceinline__ float hatf(float d) {
    return fmaxf(0.0f, 1.0f - fabsf(d));
}

__device__ __forceinline__ uint32_t packh2(float x, float y) {
    __half2 t = __floats2half2_rn(x, y);
    return *reinterpret_cast<uint32_t*>(&t);
}

// ============================================================================
// Kernel A: vproj[b,i,p,q] = sum_hw wy[h,p]*wx[w,q]*v[b,i,h,w]
//           + emit fp16 copy of v into g_vh
// grid = B*Cin, 256 threads; all 16 row-loads issued up front (MLP=16)
// v read with __ldcs (read-once, evict-first) to keep vh resident in L2.
// ============================================================================
__global__ __launch_bounds__(256) void kA_vproj(const float* __restrict__ v) {
    const int tid  = threadIdx.x;
    const int wid  = tid >> 5;
    const int lane = tid & 31;
    const float* vb = v + (size_t)blockIdx.x * HW;
    __half* vhb = g_vh + (size_t)blockIdx.x * HW;

    float wxr[4][4];
#pragma unroll
    for (int c = 0; c < 4; c++) {
        float tx = ((lane << 2) + c + 0.5f) * K3;
#pragma unroll
        for (int q = 0; q < 4; q++) wxr[c][q] = hatf(tx - (float)q);
    }

    float acc[16];
#pragma unroll
    for (int t = 0; t < 16; t++) acc[t] = 0.0f;

    // issue all 16 row loads up front for max MLP
    float4 rows[16];
#pragma unroll
    for (int rr = 0; rr < 16; rr++) {
        const int r = (wid << 4) + rr;
        rows[rr] = __ldcs(reinterpret_cast<const float4*>(vb + r * WW + (lane << 2)));
    }

#pragma unroll
    for (int rr = 0; rr < 16; rr++) {
        const int r = (wid << 4) + rr;
        const float vals[4] = {rows[rr].x, rows[rr].y, rows[rr].z, rows[rr].w};
        // fp16 copy (coalesced 8B per lane)
        uint2 hh;
        hh.x = packh2(vals[0], vals[1]);
        hh.y = packh2(vals[2], vals[3]);
        *reinterpret_cast<uint2*>(vhb + r * WW + (lane << 2)) = hh;

        float s[4] = {0.f, 0.f, 0.f, 0.f};
#pragma unroll
        for (int c = 0; c < 4; c++) {
#pragma unroll
            for (int q = 0; q < 4; q++) s[q] += vals[c] * wxr[c][q];
        }
        float ty = (r + 0.5f) * K3;
#pragma unroll
        for (int p = 0; p < 4; p++) {
            float hp = hatf(ty - (float)p);
#pragma unroll
            for (int q = 0; q < 4; q++) acc[p * 4 + q] += hp * s[q];
        }
    }

#pragma unroll
    for (int t = 0; t < 16; t++) {
#pragma unroll
        for (int off = 16; off > 0; off >>= 1)
            acc[t] += __shfl_xor_sync(0xFFFFFFFFu, acc[t], off);
    }
    __shared__ float red[8][16];
    if (lane == 0) {
#pragma unroll
        for (int t = 0; t < 16; t++) red[wid][t] = acc[t];
    }
    __syncthreads();
    if (tid < 16) {
        float s = 0.f;
#pragma unroll
        for (int w = 0; w < 8; w++) s += red[w][tid];
        g_vproj[blockIdx.x * 16 + tid] = s;
    }
}

// ============================================================================
// Kernel B1 (+ W-pack merged): grid (33, 8), 256 threads
// ============================================================================
__global__ __launch_bounds__(256) void kB1W(const float* __restrict__ k1,
                                            const float* __restrict__ cw) {
    const int tid = threadIdx.x;
    if (blockIdx.x == 32) {
        const int idx = blockIdx.y * 256 + tid;   // 0..2047
        const int ot = idx >> 8, ks = (idx >> 5) & 7, lane = idx & 31;
        const int r0 = ot * 16 + (lane >> 2), r1 = r0 + 8;
        const int kb = ks * 16 + (lane & 3) * 2;
        uint4 f;
        f.x = packh2(cw[r0 * CIN + kb],     cw[r0 * CIN + kb + 1]);
        f.y = packh2(cw[r1 * CIN + kb],     cw[r1 * CIN + kb + 1]);
        f.z = packh2(cw[r0 * CIN + kb + 8], cw[r0 * CIN + kb + 9]);
        f.w = packh2(cw[r1 * CIN + kb + 8], cw[r1 * CIN + kb + 9]);
        g_Wfrag[ot][ks][lane] = f;
        return;
    }
    const int r = blockIdx.x, b = blockIdx.y;
    const int wid = tid >> 5, lane = tid & 31;
    const float* k1p = k1 + (size_t)r * (CIN * 16);
    const float* vpp = g_vproj + (size_t)b * (CIN * 16);

    float s = 0.f;
#pragma unroll
    for (int j = 0; j < 2; j++) {
        const int e = (j * 256 + tid) * 4;
        float4 a = __ldcs(reinterpret_cast<const float4*>(k1p + e));
        float4 c = *reinterpret_cast<const float4*>(vpp + e);
        s += a.x * c.x + a.y * c.y + a.z * c.z + a.w * c.w;
    }
#pragma unroll
    for (int off = 16; off > 0; off >>= 1)
        s += __shfl_xor_sync(0xFFFFFFFFu, s, off);
    __shared__ float red[8];
    if (lane == 0) red[wid] = s;
    __syncthreads();
    if (tid == 0) {
        float t = 0.f;
#pragma unroll
        for (int w = 0; w < 8; w++) t += red[w];
        g_vr[b * RNK + r] = t * (1.0f / (float)HW);
    }
}

// ============================================================================
// Kernel B2: partial m over r-chunks of 8: grid (8, 4, B)
// ============================================================================
__global__ __launch_bounds__(256) void kB2_m(const float* __restrict__ k2) {
    const int ch = blockIdx.x, rc = blockIdx.y, b = blockIdx.z, tid = threadIdx.x;
    __shared__ float vr[8];
    if (tid < 8) vr[tid] = g_vr[b * RNK + rc * 8 + tid];
    __syncthreads();

    const int idx = ch * 256 + tid;
    float s = 0.f;
#pragma unroll
    for (int j = 0; j < 8; j++)
        s += __ldcs(&k2[(size_t)(rc * 8 + j) * (COUT * 16) + idx]) * vr[j];
    g_mpart[rc][b * (COUT * 16) + idx] = s;
}

// ============================================================================
// Kernel C: out = conv_w@v (fp16 HMMA) + interp(m) + biases
// grid = (h=128, wh=2, b=8), 256 threads (8 warps: 4 o-tiles x 2 w-tiles, 32x32)
// 4 full cp.async buffers prefetched up front; fully unrolled k-loop.
// ============================================================================

#define LDSM4T(r0, r1, r2, r3, addr)                                            \
    asm volatile("ldmatrix.sync.aligned.m8n8.x4.trans.shared.b16 {%0,%1,%2,%3}, [%4];" \
                 : "=r"(r0), "=r"(r1), "=r"(r2), "=r"(r3) : "r"(addr))

#define MMAF16(d, a0, a1, a2, a3, b0, b1)                                  \
    asm volatile("mma.sync.aligned.m16n8k16.row.col.f32.f16.f16.f32 "      \
                 "{%0,%1,%2,%3}, {%4,%5,%6,%7}, {%8,%9}, {%0,%1,%2,%3};"   \
                 : "+f"(d[0]), "+f"(d[1]), "+f"(d[2]), "+f"(d[3])          \
                 : "r"(a0), "r"(a1), "r"(a2), "r"(a3), "r"(b0), "r"(b1))

#define CP_ASYNC16(dst, src) \
    asm volatile("cp.async.cg.shared.global [%0], [%1], 16;" :: "r"(dst), "l"(src))
#define CP_COMMIT()  asm volatile("cp.async.commit_group;")
#define CP_WAIT_N(n) asm volatile("cp.async.wait_group %0;" :: "n"(n))

__global__ __launch_bounds__(256, 3) void kC_fp16(const float* __restrict__ conv_b,
                                                  const float* __restrict__ bias,
                                                  float* __restrict__ out) {
    // 4 bufs x 32 k-rows x 64 w (fp16): 128B rows, 8 chunks of 16B, XOR swizzle
    __shared__ __align__(16) __half sB[4][32][64];
    __shared__ __align__(16) float sM2[128][4];
    __shared__ float sCB[128];

    const int h = blockIdx.x, wh = blockIdx.y, b = blockIdx.z;
    const int tid = threadIdx.x, wid = tid >> 5, lane = tid & 31;
    const int o_base = (wid & 3) * 32;
    const int wloc   = (wid >> 2) * 32;
    const int ot0 = (wid & 3) * 2;

    // load slot: krow = tid>>3 (0..31), cseg = tid&7 (one 16B chunk each)
    const int krow = tid >> 3;
    const int cseg = tid & 7;
    const int sw = krow & 7;
    const __half* vhbase = g_vh + (((size_t)b * CIN + krow) * HH + h) * WW + wh * 64 + cseg * 8;
    const uint32_t sBbase = (uint32_t)__cvta_generic_to_shared(&sB[0][0][0]);
    const uint32_t mydst = (uint32_t)(krow * 128 + (cseg ^ sw) * 16);

    // issue ALL 4 chunks up front (one commit group each)
#pragma unroll
    for (int pc = 0; pc < 4; pc++) {
        CP_ASYNC16(sBbase + (uint32_t)(pc * 4096) + mydst, vhbase + (size_t)pc * 32 * HW);
        CP_COMMIT();
    }

    // prologue: M2[o][q] = sum_p wy[h,p]*m[b,o,p*4+q] (m = sum of 4 partials)
    {
        const float ty = (h + 0.5f) * K3;
        const float wy0 = hatf(ty), wy1 = hatf(ty - 1.f);
        const float wy2 = hatf(ty - 2.f), wy3 = hatf(ty - 3.f);
        for (int idx = tid; idx < 512; idx += 256) {
            const int o = idx >> 2, q = idx & 3;
            const int base = b * (COUT * 16) + o * 16 + q;
            float m0 = 0.f, m1 = 0.f, m2 = 0.f, m3 = 0.f;
#pragma unroll
            for (int rc = 0; rc < 4; rc++) {
                const float* mp = &g_mpart[rc][base];
                m0 += mp[0]; m1 += mp[4]; m2 += mp[8]; m3 += mp[12];
            }
            sM2[o][q] = wy0 * m0 + wy1 * m1 + wy2 * m2 + wy3 * m3;
        }
        if (tid < 128) sCB[tid] = conv_b[tid] + bias[tid];
    }

    float acc[2][4][4];
#pragma unroll
    for (int mi = 0; mi < 2; mi++)
#pragma unroll
        for (int ni = 0; ni < 4; ni++)
#pragma unroll
            for (int c = 0; c < 4; c++) acc[mi][ni][c] = 0.0f;

// one kc iteration; KC and WAITN are compile-time literals
#define KC_ITER(KC, WAITN)                                                     \
    {                                                                          \
        CP_WAIT_N(WAITN);                                                      \
        __syncthreads();                                                       \
        _Pragma("unroll")                                                      \
        for (int ks = 0; ks < 2; ks++) {                                       \
            const int gks = (KC) * 2 + ks;                                     \
            uint4 A0 = g_Wfrag[ot0 + 0][gks][lane];                            \
            uint4 A1 = g_Wfrag[ot0 + 1][gks][lane];                            \
            const int kr = ks * 16 + (lane & 15);                              \
            const uint32_t rowoff = (uint32_t)((KC) * 4096 + kr * 128);        \
            const int cb = (wloc >> 3) + (lane >> 4);                          \
            _Pragma("unroll")                                                  \
            for (int ng = 0; ng < 2; ng++) {                                   \
                const int chunk = (cb + ng * 2) ^ (kr & 7);                    \
                uint32_t b0, b1, b2, b3;                                       \
                LDSM4T(b0, b1, b2, b3, sBbase + rowoff + (uint32_t)(chunk * 16)); \
                float* d00 = acc[0][ng * 2 + 0];                               \
                float* d01 = acc[0][ng * 2 + 1];                               \
                float* d10 = acc[1][ng * 2 + 0];                               \
                float* d11 = acc[1][ng * 2 + 1];                               \
                MMAF16(d00, A0.x, A0.y, A0.z, A0.w, b0, b1);                   \
                MMAF16(d01, A0.x, A0.y, A0.z, A0.w, b2, b3);                   \
                MMAF16(d10, A1.x, A1.y, A1.z, A1.w, b0, b1);                   \
                MMAF16(d11, A1.x, A1.y, A1.z, A1.w, b2, b3);                   \
            }                                                                  \
        }                                                                      \
    }

    KC_ITER(0, 3)
    KC_ITER(1, 2)
    KC_ITER(2, 1)
    KC_ITER(3, 0)
#undef KC_ITER

    // epilogue: add interp term + biases, store (streaming, keep L2 for vh)
    const int g = lane >> 2, cq = lane & 3;
#pragma unroll
    for (int ni = 0; ni < 4; ni++) {
        const int w0 = wh * 64 + wloc + ni * 8 + cq * 2;
        const float tx0 = (w0 + 0.5f) * K3, tx1 = tx0 + K3;
        float wxa[4], wxb[4];
#pragma unroll
        for (int q = 0; q < 4; q++) {
            wxa[q] = hatf(tx0 - (float)q);
            wxb[q] = hatf(tx1 - (float)q);
        }
#pragma unroll
        for (int mi = 0; mi < 2; mi++) {
#pragma unroll
            for (int rr = 0; rr < 2; rr++) {
                const int o = o_base + mi * 16 + g + rr * 8;
                float4 m2 = *reinterpret_cast<float4*>(&sM2[o][0]);
                const float base = sCB[o];
                float t0 = base + wxa[0] * m2.x + wxa[1] * m2.y + wxa[2] * m2.z + wxa[3] * m2.w;
                float t1 = base + wxb[0] * m2.x + wxb[1] * m2.y + wxb[2] * m2.z + wxb[3] * m2.w;
                float2 res;
                res.x = acc[mi][ni][rr * 2 + 0] + t0;
                res.y = acc[mi][ni][rr * 2 + 1] + t1;
                __stcs(reinterpret_cast<float2*>(out + (((size_t)b * COUT + o) * HH + h) * WW + w0), res);
            }
        }
    }
}

// ============================================================================
extern "C" void kernel_launch(void* const* d_in, const int* in_sizes, int n_in,
                              void* d_out, int out_size) {
    const float* v      = (const float*)d_in[0];
    const float* k1     = (const float*)d_in[1];
    const float* k2     = (const float*)d_in[2];
    const float* conv_w = (const float*)d_in[3];
    const float* conv_b = (const float*)d_in[4];
    const float* bias   = (const float*)d_in[5];
    float* out = (float*)d_out;

    kA_vproj<<<BB * CIN, 256>>>(v);
    kB1W<<<dim3(33, BB), 256>>>(k1, conv_w);
    kB2_m<<<dim3(8, 4, BB), 256>>>(k2);
    kC_fp16<<<dim3(HH, 2, BB), 256>>>(conv_b, bias, out);
}